// round 4
// baseline (speedup 1.0000x reference)
#include <cuda_runtime.h>
#include <string.h>
#include <math.h>

#define NQ 16
#define NL 6
#define NB 512
#define TB 12                  // tile bits
#define TS (1 << TB)           // 4096 amplitudes per tile
#define NFIX (NQ - TB)         // 4 fixed bits
#define NT (1 << NFIX)         // 16 tiles per sample
#define TPB 512
#define EPT (TS / TPB)         // 8 elements per thread
#define MAXOPS 28
#define MTPB 256
#define MCHUNKS 8
#define MCHUNK ((1 << NQ) / MCHUNKS)   // 8192

struct GOp {
    int kind;       // 0 = Rot, 1 = CNOT
    int wq;         // Rot: qubit index for weight lookup
    unsigned m0;    // Rot: local pair mask; CNOT: local control mask
    unsigned m1;    // CNOT: local target mask
};

struct PassDesc {
    int fb[TB];         // global bit position of each local tile bit
    int fpos[NFIX];     // global bit positions fixed per CTA
    int nops;
    int layer;
    int synth;          // 1: synthesize post-embedding product state
    GOp ops[MAXOPS];
};

// 512 * 65536 complex64 = 256 MB scratch (static __device__: no allocation)
__device__ float2 g_state[(size_t)NB << NQ];
// per-(sample, chunk) partial expectation sums (deterministic reduction)
__device__ float g_part[NB * MCHUNKS * NQ];

__global__ void __launch_bounds__(TPB) pass_kernel(PassDesc pd,
                                                   const float* __restrict__ x,
                                                   const float* __restrict__ w)
{
    __shared__ float2 tile[TS];
    __shared__ float2 gm[MAXOPS][4];
    __shared__ float sc[NQ], ss[NQ];

    const int tid = threadIdx.x;
    const int b = blockIdx.x >> NFIX;
    const int tsel = blockIdx.x & (NT - 1);

    unsigned fofs = 0;
#pragma unroll
    for (int i = 0; i < NFIX; i++)
        fofs |= ((unsigned)(tsel >> i) & 1u) << pd.fpos[i];

    float2* st = g_state + ((size_t)b << NQ);

    // One thread per op builds the Rot matrix:
    // Rot(phi,theta,omega) = RZ(omega) RY(theta) RZ(phi)
    if (tid < pd.nops) {
        GOp op = pd.ops[tid];
        if (op.kind == 0) {
            const float* wp = w + (pd.layer * NQ + op.wq) * 3;
            float phi = wp[0], th = wp[1], om = wp[2];
            float stt, ct, sa, ca, sb, cb;
            sincosf(0.5f * th, &stt, &ct);
            sincosf(0.5f * (phi + om), &sa, &ca);
            sincosf(0.5f * (phi - om), &sb, &cb);
            gm[tid][0] = make_float2(ct * ca, -ct * sa);     // u00
            gm[tid][1] = make_float2(-stt * cb, -stt * sb);  // u01
            gm[tid][2] = make_float2(stt * cb, -stt * sb);   // u10
            gm[tid][3] = make_float2(ct * ca, ct * sa);      // u11
        }
    }
    if (pd.synth && tid < NQ)
        sincosf(0.5f * x[b * NQ + tid], &ss[tid], &sc[tid]);

    // Global offsets of this thread's EPT elements
    unsigned gofs[EPT];
#pragma unroll
    for (int e = 0; e < EPT; e++) {
        unsigned j = (unsigned)((e << 9) + tid), g = fofs;
#pragma unroll
        for (int p = 0; p < TB; p++)
            g |= ((j >> p) & 1u) << pd.fb[p];
        gofs[e] = g;
    }

    __syncthreads();

    float2 v[EPT];
    if (pd.synth) {
        // Post-AngleEmbedding product state:
        // amp(g) = (-i)^popc(g) * prod_q (bit_q ? sin(x_q/2) : cos(x_q/2))
#pragma unroll
        for (int e = 0; e < EPT; e++) {
            unsigned g = gofs[e];
            float mag = 1.0f;
#pragma unroll
            for (int q = 0; q < NQ; q++)
                mag *= ((g >> q) & 1u) ? ss[q] : sc[q];
            int k = __popc(g) & 3;
            float2 a;
            a.x = (k == 0) ? mag : ((k == 2) ? -mag : 0.0f);
            a.y = (k == 1) ? -mag : ((k == 3) ? mag : 0.0f);
            v[e] = a;
            tile[(e << 9) + tid] = a;
        }
    } else {
#pragma unroll
        for (int e = 0; e < EPT; e++) {
            float2 a = st[gofs[e]];
            v[e] = a;
            tile[(e << 9) + tid] = a;
        }
    }
    __syncthreads();

    const int nops = pd.nops;
    for (int o = 0; o < nops; o++) {
        GOp op = pd.ops[o];
        const bool last = (o == nops - 1);
        const unsigned pm = (op.kind == 0) ? op.m0 : op.m1;
        float2 pp[EPT];
#pragma unroll
        for (int e = 0; e < EPT; e++)
            pp[e] = tile[((e << 9) + tid) ^ pm];
        __syncthreads();   // all partner reads done before writes

        if (op.kind == 0) {
            const float2 u00 = gm[o][0], u01 = gm[o][1];
            const float2 u10 = gm[o][2], u11 = gm[o][3];
            const unsigned m = op.m0;
#pragma unroll
            for (int e = 0; e < EPT; e++) {
                unsigned j = (unsigned)((e << 9) + tid);
                float2 a = v[e], p = pp[e];
                bool hi = (j & m) != 0u;
                float2 lo = hi ? p : a;   // amplitude with gate bit = 0
                float2 hv = hi ? a : p;   // amplitude with gate bit = 1
                float2 ua = hi ? u10 : u00;
                float2 ub = hi ? u11 : u01;
                float2 nv;
                nv.x = ua.x * lo.x - ua.y * lo.y + ub.x * hv.x - ub.y * hv.y;
                nv.y = ua.x * lo.y + ua.y * lo.x + ub.x * hv.y + ub.y * hv.x;
                v[e] = nv;
                if (!last) tile[j] = nv;
            }
        } else {
            const unsigned cm = op.m0;
#pragma unroll
            for (int e = 0; e < EPT; e++) {
                unsigned j = (unsigned)((e << 9) + tid);
                if (j & cm) v[e] = pp[e];
                if (!last) tile[j] = v[e];
            }
        }
        if (!last) __syncthreads();   // writes visible before next op's reads
    }

#pragma unroll
    for (int e = 0; e < EPT; e++)
        st[gofs[e]] = v[e];
}

__global__ void __launch_bounds__(MTPB) measure_kernel()
{
    __shared__ float red[MTPB / 32][NQ];
    const int b = blockIdx.x / MCHUNKS;
    const int ch = blockIdx.x % MCHUNKS;
    const float2* st = g_state + ((size_t)b << NQ) + (size_t)ch * MCHUNK;
    const unsigned base = (unsigned)(ch * MCHUNK);
    const int tid = threadIdx.x;

    float acc[NQ];
#pragma unroll
    for (int q = 0; q < NQ; q++) acc[q] = 0.0f;

    for (int i = tid; i < MCHUNK; i += MTPB) {
        float2 a = st[i];
        float p = a.x * a.x + a.y * a.y;
        unsigned g = base + (unsigned)i;
#pragma unroll
        for (int q = 0; q < NQ; q++)
            acc[q] += ((g >> q) & 1u) ? -p : p;
    }
#pragma unroll
    for (int q = 0; q < NQ; q++)
#pragma unroll
        for (int o = 16; o > 0; o >>= 1)
            acc[q] += __shfl_xor_sync(0xffffffffu, acc[q], o);
    if ((tid & 31) == 0) {
#pragma unroll
        for (int q = 0; q < NQ; q++)
            red[tid >> 5][q] = acc[q];
    }
    __syncthreads();
    if (tid < NQ) {
        float s = 0.0f;
#pragma unroll
        for (int wg = 0; wg < MTPB / 32; wg++)
            s += red[wg][tid];
        g_part[blockIdx.x * NQ + tid] = s;
    }
}

__global__ void finalize_kernel(float* __restrict__ out)
{
    int i = blockIdx.x * blockDim.x + threadIdx.x;
    if (i < NB * NQ) {
        int b = i / NQ, q = i % NQ;
        float s = 0.0f;
#pragma unroll
        for (int ch = 0; ch < MCHUNKS; ch++)
            s += g_part[(b * MCHUNKS + ch) * NQ + q];
        out[i] = s;
    }
}

// ---------------------------------------------------------------------------
// Host-side scheduling: per layer l (ring range r = l+1), pass A covers
// qubits 0..11 (Rot 0..11 + all ring CNOTs inside bits 0..11), pass B covers
// the remaining touched qubits (Rot 12..15 + deferred CNOTs, original order).
// Deferral is exact: deferred CNOTs commute with every later-executed pass-A
// gate (violation needs q in [12-r, r-5], empty for r <= 6).
// ---------------------------------------------------------------------------
static void build_passes(PassDesc* pds)
{
    for (int l = 0; l < NL; l++) {
        int r = (l % (NQ - 1)) + 1;

        PassDesc& pa = pds[2 * l];
        memset(&pa, 0, sizeof(pa));
        for (int i = 0; i < TB; i++) pa.fb[i] = i;
        for (int i = 0; i < NFIX; i++) pa.fpos[i] = TB + i;
        pa.layer = l;
        pa.synth = (l == 0) ? 1 : 0;
        int n = 0;
        for (int q = 0; q < TB; q++) {
            pa.ops[n].kind = 0; pa.ops[n].wq = q;
            pa.ops[n].m0 = 1u << q; pa.ops[n].m1 = 0; n++;
        }
        bool inA[NQ];
        for (int q = 0; q < NQ; q++) {
            int t = (q + r) % NQ;
            inA[q] = (q <= 11 && t <= 11);
            if (inA[q]) {
                pa.ops[n].kind = 1; pa.ops[n].wq = 0;
                pa.ops[n].m0 = 1u << q; pa.ops[n].m1 = 1u << t; n++;
            }
        }
        pa.nops = n;

        PassDesc& pb = pds[2 * l + 1];
        memset(&pb, 0, sizeof(pb));
        pb.layer = l;
        pb.synth = 0;
        bool touched[NQ] = {};
        for (int q = 12; q < NQ; q++) touched[q] = true;
        for (int q = 0; q < NQ; q++)
            if (!inA[q]) { touched[q] = true; touched[(q + r) % NQ] = true; }
        int cnt = 0;
        for (int q = 0; q < NQ; q++) if (touched[q]) cnt++;
        for (int q = 0; q < NQ && cnt < TB; q++)
            if (!touched[q]) { touched[q] = true; cnt++; }
        int lq[NQ];
        int fi = 0, xi = 0;
        for (int q = 0; q < NQ; q++) {
            if (touched[q]) { pb.fb[fi] = q; lq[q] = fi; fi++; }
            else            { pb.fpos[xi] = q; lq[q] = -1; xi++; }
        }
        int n2 = 0;
        for (int q = 12; q < NQ; q++) {
            pb.ops[n2].kind = 0; pb.ops[n2].wq = q;
            pb.ops[n2].m0 = 1u << lq[q]; pb.ops[n2].m1 = 0; n2++;
        }
        for (int q = 0; q < NQ; q++) {
            if (!inA[q]) {
                int t = (q + r) % NQ;
                pb.ops[n2].kind = 1; pb.ops[n2].wq = 0;
                pb.ops[n2].m0 = 1u << lq[q]; pb.ops[n2].m1 = 1u << lq[t]; n2++;
            }
        }
        pb.nops = n2;
    }
}

extern "C" void kernel_launch(void* const* d_in, const int* in_sizes, int n_in,
                              void* d_out, int out_size)
{
    const float* x = (const float*)d_in[0];   // (512, 16)
    const float* w = (const float*)d_in[1];   // (6, 16, 3)
    float* out = (float*)d_out;               // (512, 16) float32

    PassDesc pds[2 * NL];
    build_passes(pds);

    dim3 grid(NB * NT);
    for (int p = 0; p < 2 * NL; p++)
        pass_kernel<<<grid, TPB>>>(pds[p], x, w);

    measure_kernel<<<NB * MCHUNKS, MTPB>>>();
    finalize_kernel<<<(NB * NQ + 255) / 256, 256>>>(out);
}

// round 5
// speedup vs baseline: 2.2421x; 2.2421x over previous
#include <cuda_runtime.h>
#include <string.h>
#include <math.h>

typedef unsigned long long u64;
typedef unsigned u32;

#define NQ 16
#define NL 6
#define NB 512
#define TB 12
#define TS 4096
#define NFIX 4
#define NT 16
#define TPB 512
#define EPT 8
#define TPAD 4608   // TS + TS/8 skew padding

struct PassDesc {
    int fb[TB];        // global bit of each local tile bit (ascending)
    int fpos[NFIX];    // global bits fixed per CTA
    int rotq[TB];      // qubit whose Rot acts on local bit lb, or -1
    u32 grow[TB];      // G(1<<lb): composed-CNOT-permutation basis images (local)
    int nphases;       // 4 (pass A) or 2 (pass B)
    int layer;
    int synth;         // synthesize post-embedding product state
    int measure;       // last pass: fuse <Z_q> accumulation, no state write
};

// 512 * 65536 complex64 = 256 MB scratch (static __device__: no allocation)
__device__ float2 g_state[(size_t)NB << NQ];
// per-CTA partial expectation sums (deterministic reduction)
__device__ float g_part[NB * NT * NQ];

__device__ __forceinline__ u64 f2fma(u64 a, u64 b, u64 c) {
    u64 d; asm("fma.rn.f32x2 %0,%1,%2,%3;" : "=l"(d) : "l"(a), "l"(b), "l"(c)); return d;
}
__device__ __forceinline__ u64 f2mul(u64 a, u64 b) {
    u64 d; asm("mul.rn.f32x2 %0,%1,%2;" : "=l"(d) : "l"(a), "l"(b)); return d;
}
__device__ __forceinline__ u64 swap64(u64 v) {
    u32 lo, hi; asm("mov.b64 {%0,%1},%2;" : "=r"(lo), "=r"(hi) : "l"(v));
    u64 o; asm("mov.b64 %0,{%1,%2};" : "=l"(o) : "r"(hi), "r"(lo)); return o;
}
__device__ __forceinline__ u64 pack2(float lo, float hi) {
    u64 o; asm("mov.b64 %0,{%1,%2};" : "=l"(o) : "f"(lo), "f"(hi)); return o;
}

// local index of element (e, tid) in phase ph (private bits: ph0={9,10,11},
// ph1={6,7,8}, ph2={3,4,5}, ph3={0,1,2})
__device__ __forceinline__ int jmap(int ph, int e, int tid) {
    switch (ph) {
        case 0:  return (e << 9) | tid;
        case 1:  return (tid & 63) | (e << 6) | ((tid >> 6) << 9);
        case 2:  return (tid & 7) | (e << 3) | ((tid >> 3) << 6);
        default: return e | (tid << 3);
    }
}

__global__ void __launch_bounds__(TPB, 2) pass_kernel(PassDesc pd,
    const float* __restrict__ x, const float* __restrict__ w)
{
    __shared__ u64 tile[TPAD];
    __shared__ u64 gmx[TB][8];
    __shared__ float sc[NQ], ss[NQ];
    __shared__ float wred[TPB / 32][NQ];

    const int tid = threadIdx.x;
    const int b = blockIdx.x >> 4;
    const int tsel = blockIdx.x & 15;

    u32 fofs = 0;
#pragma unroll
    for (int i = 0; i < NFIX; i++)
        fofs |= ((u32)(tsel >> i) & 1u) << pd.fpos[i];

    // gbase: fixed offset + tid bits 0..8 spread onto fb[0..8]
    u32 gbase = fofs;
#pragma unroll
    for (int lb = 0; lb < 9; lb++)
        gbase |= ((u32)(tid >> lb) & 1u) << pd.fb[lb];
    const u32 f9 = 1u << pd.fb[9], f10 = 1u << pd.fb[10], f11 = 1u << pd.fb[11];

    // One thread per Rot builds packed f32x2 gate constants:
    // Rot(phi,theta,omega) = RZ(omega) RY(theta) RZ(phi)
    if (tid < TB) {
        int q = pd.rotq[tid];
        if (q >= 0) {
            const float* wp = w + (pd.layer * NQ + q) * 3;
            float phi = wp[0], th = wp[1], om = wp[2];
            float stt, ct, sa, ca, sb, cb;
            sincosf(0.5f * th, &stt, &ct);
            sincosf(0.5f * (phi + om), &sa, &ca);
            sincosf(0.5f * (phi - om), &sb, &cb);
            float u00r =  ct * ca, u00i = -ct * sa;
            float u01r = -stt * cb, u01i = -stt * sb;
            float u10r =  stt * cb, u10i = -stt * sb;
            float u11r =  ct * ca, u11i =  ct * sa;
            gmx[tid][0] = pack2(u00r, u00r); gmx[tid][1] = pack2(-u00i, u00i);
            gmx[tid][2] = pack2(u01r, u01r); gmx[tid][3] = pack2(-u01i, u01i);
            gmx[tid][4] = pack2(u10r, u10r); gmx[tid][5] = pack2(-u10i, u10i);
            gmx[tid][6] = pack2(u11r, u11r); gmx[tid][7] = pack2(-u11i, u11i);
        }
    }
    if (pd.synth && tid < NQ)
        sincosf(0.5f * x[b * NQ + tid], &ss[tid], &sc[tid]);

    u64* stg = (u64*)g_state + ((size_t)b << NQ);
    u64 v[EPT];

    if (!pd.synth) {
#pragma unroll
        for (int e = 0; e < EPT; e++) {
            u32 g = gbase | ((e & 1) ? f9 : 0u) | ((e & 2) ? f10 : 0u) | ((e & 4) ? f11 : 0u);
            v[e] = stg[g];
        }
    }
    __syncthreads();
    if (pd.synth) {
        // amp(g) = (-i)^popc(g) * prod_q (bit_q ? sin(x_q/2) : cos(x_q/2))
#pragma unroll
        for (int e = 0; e < EPT; e++) {
            u32 g = gbase | ((e & 1) ? f9 : 0u) | ((e & 2) ? f10 : 0u) | ((e & 4) ? f11 : 0u);
            float mag = 1.0f;
#pragma unroll
            for (int q = 0; q < NQ; q++)
                mag *= ((g >> q) & 1u) ? ss[q] : sc[q];
            int k = __popc(g) & 3;
            float re = (k == 0) ? mag : ((k == 2) ? -mag : 0.0f);
            float im = (k == 1) ? -mag : ((k == 3) ? mag : 0.0f);
            v[e] = pack2(re, im);
        }
    }

    const int nph = pd.nphases;
    for (int ph = 0; ph < nph; ph++) {
        if (ph > 0) {
#pragma unroll
            for (int e = 0; e < EPT; e++) {
                int j = jmap(ph, e, tid);
                v[e] = tile[j + (j >> 3)];
            }
        }
        const int lb0 = 9 - 3 * ph;
#pragma unroll
        for (int s = 0; s < 3; s++) {
            int lb = lb0 + s;
            if (pd.rotq[lb] >= 0) {
                u64 c00r = gmx[lb][0], c00i = gmx[lb][1], c01r = gmx[lb][2], c01i = gmx[lb][3];
                u64 c10r = gmx[lb][4], c10i = gmx[lb][5], c11r = gmx[lb][6], c11i = gmx[lb][7];
#pragma unroll
                for (int p = 0; p < 4; p++) {
                    int elo = ((p >> s) << (s + 1)) | (p & ((1 << s) - 1));
                    int ehi = elo | (1 << s);
                    u64 a = v[elo], bb = v[ehi];
                    u64 sa_ = swap64(a), sb_ = swap64(bb);
                    v[elo] = f2fma(c00r, a, f2fma(c00i, sa_, f2fma(c01r, bb, f2mul(c01i, sb_))));
                    v[ehi] = f2fma(c10r, a, f2fma(c10i, sa_, f2fma(c11r, bb, f2mul(c11i, sb_))));
                }
            }
        }
        if (ph > 0) __syncthreads();   // all tile reads done before overwrite
#pragma unroll
        for (int e = 0; e < EPT; e++) {
            int j = jmap(ph, e, tid);
            tile[j + (j >> 3)] = v[e];
        }
        __syncthreads();
    }

    // sigma gather: f[j] = s[G(j)], G = composed CNOT chain (XOR-linear)
    u32 srcbase = 0;
#pragma unroll
    for (int lb = 0; lb < 9; lb++)
        if ((tid >> lb) & 1) srcbase ^= pd.grow[lb];
    const u32 g9 = pd.grow[9], g10 = pd.grow[10], g11 = pd.grow[11];

    if (!pd.measure) {
#pragma unroll
        for (int e = 0; e < EPT; e++) {
            u32 src = srcbase ^ ((e & 1) ? g9 : 0u) ^ ((e & 2) ? g10 : 0u) ^ ((e & 4) ? g11 : 0u);
            u32 g = gbase | ((e & 1) ? f9 : 0u) | ((e & 2) ? f10 : 0u) | ((e & 4) ? f11 : 0u);
            stg[g] = tile[src + (src >> 3)];
        }
    } else {
        float p8[EPT];
#pragma unroll
        for (int e = 0; e < EPT; e++) {
            u32 src = srcbase ^ ((e & 1) ? g9 : 0u) ^ ((e & 2) ? g10 : 0u) ^ ((e & 4) ? g11 : 0u);
            u64 val = tile[src + (src >> 3)];
            float2 c = *(float2*)&val;
            p8[e] = c.x * c.x + c.y * c.y;
        }
        float a0 = p8[0] + p8[1], a1 = p8[2] + p8[3], a2 = p8[4] + p8[5], a3 = p8[6] + p8[7];
        float b0 = a0 + a1, b1 = a2 + a3;
        float s_ = b0 + b1;
        float z0 = (p8[0] - p8[1]) + (p8[2] - p8[3]) + (p8[4] - p8[5]) + (p8[6] - p8[7]);
        float z1 = (a0 - a1) + (a2 - a3);
        float z2 = b0 - b1;
        float acc[NQ];
#pragma unroll
        for (int q = 0; q < NQ; q++) {
            float t = ((gbase >> q) & 1u) ? -s_ : s_;
            if (q == pd.fb[9])  t = z0;   // gbase bit is 0 there; z already signed
            if (q == pd.fb[10]) t = z1;
            if (q == pd.fb[11]) t = z2;
            acc[q] = t;
        }
#pragma unroll
        for (int q = 0; q < NQ; q++)
#pragma unroll
            for (int o = 16; o > 0; o >>= 1)
                acc[q] += __shfl_xor_sync(0xffffffffu, acc[q], o);
        if ((tid & 31) == 0) {
#pragma unroll
            for (int q = 0; q < NQ; q++)
                wred[tid >> 5], wred[tid >> 5][q] = acc[q];
        }
        __syncthreads();
        if (tid < NQ) {
            float sm = 0.0f;
#pragma unroll
            for (int wg = 0; wg < TPB / 32; wg++)
                sm += wred[wg][tid];
            g_part[blockIdx.x * NQ + tid] = sm;
        }
    }
}

__global__ void finalize_kernel(float* __restrict__ out)
{
    int i = blockIdx.x * blockDim.x + threadIdx.x;
    if (i < NB * NQ) {
        int b = i / NQ, q = i % NQ;
        float s = 0.0f;
#pragma unroll
        for (int t = 0; t < NT; t++)
            s += g_part[(b * NT + t) * NQ + q];
        out[i] = s;
    }
}

// ---------------------------------------------------------------------------
// Host scheduling (same exact 2-pass split proven in R3/R4): per layer l
// (r = l+1), pass A = Rot 0..11 + in-tile ring CNOTs; pass B = Rot 12..15 +
// deferred CNOTs. CNOT chain of each pass is composed into grow[] (apply
// the chain in REVERSE to each basis vector: G(j) = g_first(...g_last(j))).
// ---------------------------------------------------------------------------
static void compose_cnots(u32* grow, const u32* cm, const u32* tm, int ncn)
{
    for (int lb = 0; lb < TB; lb++) {
        u32 s = 1u << lb;
        for (int i = ncn - 1; i >= 0; i--)
            if (s & cm[i]) s ^= tm[i];
        grow[lb] = s;
    }
}

static void build_passes(PassDesc* pds)
{
    for (int l = 0; l < NL; l++) {
        int r = (l % (NQ - 1)) + 1;
        bool inA[NQ];
        for (int q = 0; q < NQ; q++) {
            int t = (q + r) % NQ;
            inA[q] = (q <= 11 && t <= 11);
        }

        // ---- pass A ----
        PassDesc& pa = pds[2 * l];
        memset(&pa, 0, sizeof(pa));
        for (int i = 0; i < TB; i++) { pa.fb[i] = i; pa.rotq[i] = i; }
        for (int i = 0; i < NFIX; i++) pa.fpos[i] = TB + i;
        pa.layer = l; pa.synth = (l == 0); pa.measure = 0; pa.nphases = 4;
        {
            u32 cm[TB], tm[TB]; int n = 0;
            for (int q = 0; q < NQ; q++)
                if (inA[q]) { cm[n] = 1u << q; tm[n] = 1u << ((q + r) % NQ); n++; }
            compose_cnots(pa.grow, cm, tm, n);
        }

        // ---- pass B ----
        PassDesc& pb = pds[2 * l + 1];
        memset(&pb, 0, sizeof(pb));
        pb.layer = l; pb.synth = 0; pb.measure = (l == NL - 1); pb.nphases = 2;
        bool touched[NQ] = {};
        for (int q = 12; q < NQ; q++) touched[q] = true;
        for (int q = 0; q < NQ; q++)
            if (!inA[q]) { touched[q] = true; touched[(q + r) % NQ] = true; }
        int cnt = 0;
        for (int q = 0; q < NQ; q++) if (touched[q]) cnt++;
        for (int q = 0; q < NQ && cnt < TB; q++)
            if (!touched[q]) { touched[q] = true; cnt++; }
        int lq[NQ];
        int fi = 0, xi = 0;
        for (int q = 0; q < NQ; q++) {
            if (touched[q]) { pb.fb[fi] = q; lq[q] = fi; fi++; }
            else            { pb.fpos[xi] = q; lq[q] = -1; xi++; }
        }
        for (int i = 0; i < TB; i++) pb.rotq[i] = -1;
        for (int q = 12; q < NQ; q++) pb.rotq[lq[q]] = q;   // lands on local 8..11
        {
            u32 cm[TB], tm[TB]; int n = 0;
            for (int q = 0; q < NQ; q++)
                if (!inA[q]) { cm[n] = 1u << lq[q]; tm[n] = 1u << lq[(q + r) % NQ]; n++; }
            compose_cnots(pb.grow, cm, tm, n);
        }
    }
}

extern "C" void kernel_launch(void* const* d_in, const int* in_sizes, int n_in,
                              void* d_out, int out_size)
{
    const float* x = (const float*)d_in[0];   // (512, 16)
    const float* w = (const float*)d_in[1];   // (6, 16, 3)
    float* out = (float*)d_out;               // (512, 16) float32

    PassDesc pds[2 * NL];
    build_passes(pds);

    dim3 grid(NB * NT);
    for (int p = 0; p < 2 * NL; p++)
        pass_kernel<<<grid, TPB>>>(pds[p], x, w);

    finalize_kernel<<<(NB * NQ + 255) / 256, 256>>>(out);
}

// round 6
// speedup vs baseline: 3.7171x; 1.6579x over previous
#include <cuda_runtime.h>
#include <string.h>
#include <math.h>

typedef unsigned long long u64;
typedef unsigned u32;

#define NQ 16
#define NL 6
#define NB 512
#define TB 12
#define TS 4096
#define NFIX 4
#define NT 16
#define TPB 512
#define EPT 8
#define TPAD 4608   // TS + TS/8 skew padding

struct PassDesc {
    int fb[TB];        // global bit of each local tile bit (ascending)
    int fpos[NFIX];    // global bits fixed per CTA
    int rotq[TB];      // qubit whose Rot acts on local bit lb, or -1
    u32 grow[TB];      // G(1<<lb): composed-CNOT-permutation basis images (local)
    int nphases;       // 4 (pass A) or 2 (pass B)
    int layer;
    int synth;         // synthesize post-embedding product state
    int measure;       // last pass: fuse <Z_q> accumulation, no state write
};

// 512 * 65536 complex64 = 256 MB scratch (static __device__: no allocation)
__device__ float2 g_state[(size_t)NB << NQ];
// per-CTA partial expectation sums (deterministic reduction)
__device__ float g_part[NB * NT * NQ];

__device__ __forceinline__ u64 f2fma(u64 a, u64 b, u64 c) {
    u64 d; asm("fma.rn.f32x2 %0,%1,%2,%3;" : "=l"(d) : "l"(a), "l"(b), "l"(c)); return d;
}
__device__ __forceinline__ u64 f2mul(u64 a, u64 b) {
    u64 d; asm("mul.rn.f32x2 %0,%1,%2;" : "=l"(d) : "l"(a), "l"(b)); return d;
}
__device__ __forceinline__ u64 swap64(u64 v) {
    u32 lo, hi; asm("mov.b64 {%0,%1},%2;" : "=r"(lo), "=r"(hi) : "l"(v));
    u64 o; asm("mov.b64 %0,{%1,%2};" : "=l"(o) : "r"(hi), "r"(lo)); return o;
}
__device__ __forceinline__ u64 pack2(float lo, float hi) {
    u64 o; asm("mov.b64 %0,{%1,%2};" : "=l"(o) : "f"(lo), "f"(hi)); return o;
}

// local index of element (e, tid) in phase ph (private bits: ph0={9,10,11},
// ph1={6,7,8}, ph2={3,4,5}, ph3={0,1,2})
__device__ __forceinline__ int jmap(int ph, int e, int tid) {
    switch (ph) {
        case 0:  return (e << 9) | tid;
        case 1:  return (tid & 63) | (e << 6) | ((tid >> 6) << 9);
        case 2:  return (tid & 7) | (e << 3) | ((tid >> 3) << 6);
        default: return e | (tid << 3);
    }
}

__global__ void __launch_bounds__(TPB, 2) pass_kernel(PassDesc pd,
    const float* __restrict__ x, const float* __restrict__ w)
{
    __shared__ u64 tile[TPAD];
    __shared__ u64 gmx[TB][8];
    __shared__ float sc[NQ], ss[NQ];
    __shared__ float wred[TPB / 32][NQ];

    const int tid = threadIdx.x;
    const int b = blockIdx.x >> 4;
    const int tsel = blockIdx.x & 15;

    u32 fofs = 0;
#pragma unroll
    for (int i = 0; i < NFIX; i++)
        fofs |= ((u32)(tsel >> i) & 1u) << pd.fpos[i];

    // gbase: fixed offset + tid bits 0..8 spread onto fb[0..8]
    u32 gbase = fofs;
#pragma unroll
    for (int lb = 0; lb < 9; lb++)
        gbase |= ((u32)(tid >> lb) & 1u) << pd.fb[lb];
    const u32 f9 = 1u << pd.fb[9], f10 = 1u << pd.fb[10], f11 = 1u << pd.fb[11];

    // One thread per Rot builds packed f32x2 gate constants:
    // Rot(phi,theta,omega) = RZ(omega) RY(theta) RZ(phi)
    if (tid < TB) {
        int q = pd.rotq[tid];
        if (q >= 0) {
            const float* wp = w + (pd.layer * NQ + q) * 3;
            float phi = wp[0], th = wp[1], om = wp[2];
            float stt, ct, sa, ca, sb, cb;
            sincosf(0.5f * th, &stt, &ct);
            sincosf(0.5f * (phi + om), &sa, &ca);
            sincosf(0.5f * (phi - om), &sb, &cb);
            float u00r =  ct * ca, u00i = -ct * sa;
            float u01r = -stt * cb, u01i = -stt * sb;
            float u10r =  stt * cb, u10i = -stt * sb;
            float u11r =  ct * ca, u11i =  ct * sa;
            gmx[tid][0] = pack2(u00r, u00r); gmx[tid][1] = pack2(-u00i, u00i);
            gmx[tid][2] = pack2(u01r, u01r); gmx[tid][3] = pack2(-u01i, u01i);
            gmx[tid][4] = pack2(u10r, u10r); gmx[tid][5] = pack2(-u10i, u10i);
            gmx[tid][6] = pack2(u11r, u11r); gmx[tid][7] = pack2(-u11i, u11i);
        }
    }
    if (pd.synth && tid < NQ)
        sincosf(0.5f * x[b * NQ + tid], &ss[tid], &sc[tid]);

    u64* stg = (u64*)g_state + ((size_t)b << NQ);
    u64 v[EPT];

    if (!pd.synth) {
#pragma unroll
        for (int e = 0; e < EPT; e++) {
            u32 g = gbase | ((e & 1) ? f9 : 0u) | ((e & 2) ? f10 : 0u) | ((e & 4) ? f11 : 0u);
            v[e] = stg[g];
        }
    }
    __syncthreads();
    if (pd.synth) {
        // amp(g) = (-i)^popc(g) * prod_q (bit_q ? sin(x_q/2) : cos(x_q/2))
#pragma unroll
        for (int e = 0; e < EPT; e++) {
            u32 g = gbase | ((e & 1) ? f9 : 0u) | ((e & 2) ? f10 : 0u) | ((e & 4) ? f11 : 0u);
            float mag = 1.0f;
#pragma unroll
            for (int q = 0; q < NQ; q++)
                mag *= ((g >> q) & 1u) ? ss[q] : sc[q];
            int k = __popc(g) & 3;
            float re = (k == 0) ? mag : ((k == 2) ? -mag : 0.0f);
            float im = (k == 1) ? -mag : ((k == 3) ? mag : 0.0f);
            v[e] = pack2(re, im);
        }
    }

    const int nph = pd.nphases;
    for (int ph = 0; ph < nph; ph++) {
        if (ph > 0) {
#pragma unroll
            for (int e = 0; e < EPT; e++) {
                int j = jmap(ph, e, tid);
                v[e] = tile[j + (j >> 3)];
            }
        }
        const int lb0 = 9 - 3 * ph;
#pragma unroll
        for (int s = 0; s < 3; s++) {
            int lb = lb0 + s;
            if (pd.rotq[lb] >= 0) {
                u64 c00r = gmx[lb][0], c00i = gmx[lb][1], c01r = gmx[lb][2], c01i = gmx[lb][3];
                u64 c10r = gmx[lb][4], c10i = gmx[lb][5], c11r = gmx[lb][6], c11i = gmx[lb][7];
#pragma unroll
                for (int p = 0; p < 4; p++) {
                    int elo = ((p >> s) << (s + 1)) | (p & ((1 << s) - 1));
                    int ehi = elo | (1 << s);
                    u64 a = v[elo], bb = v[ehi];
                    u64 sa_ = swap64(a), sb_ = swap64(bb);
                    v[elo] = f2fma(c00r, a, f2fma(c00i, sa_, f2fma(c01r, bb, f2mul(c01i, sb_))));
                    v[ehi] = f2fma(c10r, a, f2fma(c10i, sa_, f2fma(c11r, bb, f2mul(c11i, sb_))));
                }
            }
        }
        if (ph > 0) __syncthreads();   // all tile reads done before overwrite
#pragma unroll
        for (int e = 0; e < EPT; e++) {
            int j = jmap(ph, e, tid);
            tile[j + (j >> 3)] = v[e];
        }
        __syncthreads();
    }

    // sigma gather: f[j] = s[G(j)], G = composed CNOT chain (XOR-linear)
    u32 srcbase = 0;
#pragma unroll
    for (int lb = 0; lb < 9; lb++)
        if ((tid >> lb) & 1) srcbase ^= pd.grow[lb];
    const u32 g9 = pd.grow[9], g10 = pd.grow[10], g11 = pd.grow[11];

    if (!pd.measure) {
#pragma unroll
        for (int e = 0; e < EPT; e++) {
            u32 src = srcbase ^ ((e & 1) ? g9 : 0u) ^ ((e & 2) ? g10 : 0u) ^ ((e & 4) ? g11 : 0u);
            u32 g = gbase | ((e & 1) ? f9 : 0u) | ((e & 2) ? f10 : 0u) | ((e & 4) ? f11 : 0u);
            stg[g] = tile[src + (src >> 3)];
        }
    } else {
        float p8[EPT];
#pragma unroll
        for (int e = 0; e < EPT; e++) {
            u32 src = srcbase ^ ((e & 1) ? g9 : 0u) ^ ((e & 2) ? g10 : 0u) ^ ((e & 4) ? g11 : 0u);
            u64 val = tile[src + (src >> 3)];
            float2 c = *(float2*)&val;
            p8[e] = c.x * c.x + c.y * c.y;
        }
        float a0 = p8[0] + p8[1], a1 = p8[2] + p8[3], a2 = p8[4] + p8[5], a3 = p8[6] + p8[7];
        float b0 = a0 + a1, b1 = a2 + a3;
        float s_ = b0 + b1;
        float z0 = (p8[0] - p8[1]) + (p8[2] - p8[3]) + (p8[4] - p8[5]) + (p8[6] - p8[7]);
        float z1 = (a0 - a1) + (a2 - a3);
        float z2 = b0 - b1;
        float acc[NQ];
#pragma unroll
        for (int q = 0; q < NQ; q++) {
            float t = ((gbase >> q) & 1u) ? -s_ : s_;
            if (q == pd.fb[9])  t = z0;   // gbase bit is 0 there; z already signed
            if (q == pd.fb[10]) t = z1;
            if (q == pd.fb[11]) t = z2;
            acc[q] = t;
        }
#pragma unroll
        for (int q = 0; q < NQ; q++)
#pragma unroll
            for (int o = 16; o > 0; o >>= 1)
                acc[q] += __shfl_xor_sync(0xffffffffu, acc[q], o);
        if ((tid & 31) == 0) {
#pragma unroll
            for (int q = 0; q < NQ; q++)
                wred[tid >> 5], wred[tid >> 5][q] = acc[q];
        }
        __syncthreads();
        if (tid < NQ) {
            float sm = 0.0f;
#pragma unroll
            for (int wg = 0; wg < TPB / 32; wg++)
                sm += wred[wg][tid];
            g_part[blockIdx.x * NQ + tid] = sm;
        }
    }
}

__global__ void finalize_kernel(float* __restrict__ out)
{
    int i = blockIdx.x * blockDim.x + threadIdx.x;
    if (i < NB * NQ) {
        int b = i / NQ, q = i % NQ;
        float s = 0.0f;
#pragma unroll
        for (int t = 0; t < NT; t++)
            s += g_part[(b * NT + t) * NQ + q];
        out[i] = s;
    }
}

// ---------------------------------------------------------------------------
// Host scheduling (same exact 2-pass split proven in R3/R4): per layer l
// (r = l+1), pass A = Rot 0..11 + in-tile ring CNOTs; pass B = Rot 12..15 +
// deferred CNOTs. CNOT chain of each pass is composed into grow[] (apply
// the chain in REVERSE to each basis vector: G(j) = g_first(...g_last(j))).
// ---------------------------------------------------------------------------
static void compose_cnots(u32* grow, const u32* cm, const u32* tm, int ncn)
{
    for (int lb = 0; lb < TB; lb++) {
        u32 s = 1u << lb;
        for (int i = ncn - 1; i >= 0; i--)
            if (s & cm[i]) s ^= tm[i];
        grow[lb] = s;
    }
}

static void build_passes(PassDesc* pds)
{
    for (int l = 0; l < NL; l++) {
        int r = (l % (NQ - 1)) + 1;
        bool inA[NQ];
        for (int q = 0; q < NQ; q++) {
            int t = (q + r) % NQ;
            inA[q] = (q <= 11 && t <= 11);
        }

        // ---- pass A ----
        PassDesc& pa = pds[2 * l];
        memset(&pa, 0, sizeof(pa));
        for (int i = 0; i < TB; i++) { pa.fb[i] = i; pa.rotq[i] = i; }
        for (int i = 0; i < NFIX; i++) pa.fpos[i] = TB + i;
        pa.layer = l; pa.synth = (l == 0); pa.measure = 0; pa.nphases = 4;
        {
            u32 cm[TB], tm[TB]; int n = 0;
            for (int q = 0; q < NQ; q++)
                if (inA[q]) { cm[n] = 1u << q; tm[n] = 1u << ((q + r) % NQ); n++; }
            compose_cnots(pa.grow, cm, tm, n);
        }

        // ---- pass B ----
        PassDesc& pb = pds[2 * l + 1];
        memset(&pb, 0, sizeof(pb));
        pb.layer = l; pb.synth = 0; pb.measure = (l == NL - 1); pb.nphases = 2;
        bool touched[NQ] = {};
        for (int q = 12; q < NQ; q++) touched[q] = true;
        for (int q = 0; q < NQ; q++)
            if (!inA[q]) { touched[q] = true; touched[(q + r) % NQ] = true; }
        int cnt = 0;
        for (int q = 0; q < NQ; q++) if (touched[q]) cnt++;
        for (int q = 0; q < NQ && cnt < TB; q++)
            if (!touched[q]) { touched[q] = true; cnt++; }
        int lq[NQ];
        int fi = 0, xi = 0;
        for (int q = 0; q < NQ; q++) {
            if (touched[q]) { pb.fb[fi] = q; lq[q] = fi; fi++; }
            else            { pb.fpos[xi] = q; lq[q] = -1; xi++; }
        }
        for (int i = 0; i < TB; i++) pb.rotq[i] = -1;
        for (int q = 12; q < NQ; q++) pb.rotq[lq[q]] = q;   // lands on local 8..11
        {
            u32 cm[TB], tm[TB]; int n = 0;
            for (int q = 0; q < NQ; q++)
                if (!inA[q]) { cm[n] = 1u << lq[q]; tm[n] = 1u << lq[(q + r) % NQ]; n++; }
            compose_cnots(pb.grow, cm, tm, n);
        }
    }
}

extern "C" void kernel_launch(void* const* d_in, const int* in_sizes, int n_in,
                              void* d_out, int out_size)
{
    const float* x = (const float*)d_in[0];   // (512, 16)
    const float* w = (const float*)d_in[1];   // (6, 16, 3)
    float* out = (float*)d_out;               // (512, 16) float32

    PassDesc pds[2 * NL];
    build_passes(pds);

    dim3 grid(NB * NT);
    for (int p = 0; p < 2 * NL; p++)
        pass_kernel<<<grid, TPB>>>(pds[p], x, w);

    finalize_kernel<<<(NB * NQ + 255) / 256, 256>>>(out);
}

// round 8
// speedup vs baseline: 3.8866x; 1.0456x over previous
#include <cuda_runtime.h>
#include <string.h>
#include <math.h>

typedef unsigned long long u64;
typedef unsigned u32;

#define NQ 16
#define NL 6
#define NB 512
#define TB 12
#define TS 4096
#define NFIX 4
#define NT 16
#define TPB 512
#define EPT 8
#define TPAD 4608   // TS + TS/8 skew padding
#define NPASS (2 * NL)
#define SKEW(j) ((j) + ((j) >> 3))

struct PassDesc {
    int fb[TB];          // global qubit of each local tile bit
    int fpos[NFIX];      // global qubit of each fixed bit
    int outpos[TB];      // address-bit of local bit i in NEXT pass layout
    int outfixpos[NFIX];
    int rotq[TB];        // qubit whose Rot acts on local bit lb, or -1
    u32 grow[TB];        // composed-CNOT basis images (local space)
    int nphases;         // 4 (pass A) or 2 (pass B)
    int layer;
    int synth;
    int measure;
    int rev;             // reverse CTA traversal (L2 locality)
};

// 512 * 65536 complex64 = 256 MB scratch (static __device__: no allocation)
__device__ float2 g_state[(size_t)NB << NQ];
__device__ float g_part[NB * NT * NQ];

__device__ __forceinline__ u64 f2fma(u64 a, u64 b, u64 c) {
    u64 d; asm("fma.rn.f32x2 %0,%1,%2,%3;" : "=l"(d) : "l"(a), "l"(b), "l"(c)); return d;
}
__device__ __forceinline__ u64 f2mul(u64 a, u64 b) {
    u64 d; asm("mul.rn.f32x2 %0,%1,%2;" : "=l"(d) : "l"(a), "l"(b)); return d;
}
__device__ __forceinline__ u64 swap64(u64 v) {
    u32 lo, hi; asm("mov.b64 {%0,%1},%2;" : "=r"(lo), "=r"(hi) : "l"(v));
    u64 o; asm("mov.b64 %0,{%1,%2};" : "=l"(o) : "r"(hi), "r"(lo)); return o;
}
__device__ __forceinline__ u64 pack2(float lo, float hi) {
    u64 o; asm("mov.b64 %0,{%1,%2};" : "=l"(o) : "f"(lo), "f"(hi)); return o;
}

// local index of element (e, tid) in phase ph (private bits: ph0={9,10,11},
// ph1={6,7,8}, ph2={3,4,5}, ph3={0,1,2})
__device__ __forceinline__ int jmap(int ph, int e, int tid) {
    switch (ph) {
        case 0:  return (e << 9) | tid;
        case 1:  return (tid & 63) | (e << 6) | ((tid >> 6) << 9);
        case 2:  return (tid & 7) | (e << 3) | ((tid >> 3) << 6);
        default: return e | (tid << 3);
    }
}

__global__ void __launch_bounds__(TPB, 2) pass_kernel(PassDesc pd,
    const float* __restrict__ x, const float* __restrict__ w)
{
    __shared__ u64 tile[TPAD];
    __shared__ u64 gmx[TB][8];
    __shared__ float sc[NQ], ss[NQ];
    __shared__ float wred[TPB / 32][NQ];

    const int tid = threadIdx.x;
    const int idx = pd.rev ? ((int)gridDim.x - 1 - (int)blockIdx.x) : (int)blockIdx.x;
    const int b = idx >> 4;
    const int tsel = idx & 15;

    // One thread per Rot builds packed f32x2 gate constants:
    // Rot(phi,theta,omega) = RZ(omega) RY(theta) RZ(phi)
    if (tid < TB) {
        int q = pd.rotq[tid];
        if (q >= 0) {
            const float* wp = w + (pd.layer * NQ + q) * 3;
            float phi = wp[0], th = wp[1], om = wp[2];
            float stt, ct, sa, ca, sb, cb;
            sincosf(0.5f * th, &stt, &ct);
            sincosf(0.5f * (phi + om), &sa, &ca);
            sincosf(0.5f * (phi - om), &sb, &cb);
            float u00r =  ct * ca, u00i = -ct * sa;
            float u01r = -stt * cb, u01i = -stt * sb;
            float u10r =  stt * cb, u10i = -stt * sb;
            float u11r =  ct * ca, u11i =  ct * sa;
            gmx[tid][0] = pack2(u00r, u00r); gmx[tid][1] = pack2(-u00i, u00i);
            gmx[tid][2] = pack2(u01r, u01r); gmx[tid][3] = pack2(-u01i, u01i);
            gmx[tid][4] = pack2(u10r, u10r); gmx[tid][5] = pack2(-u10i, u10i);
            gmx[tid][6] = pack2(u11r, u11r); gmx[tid][7] = pack2(-u11i, u11i);
        }
    }
    if (pd.synth && tid < NQ)
        sincosf(0.5f * x[b * NQ + tid], &ss[tid], &sc[tid]);

    u64* stg = (u64*)g_state + ((size_t)b << NQ);
    u64 v[EPT];

    if (!pd.synth) {
        // Linear read: this pass's layout has its free bits at addr bits 0..11
        // (the previous pass wrote the state in THIS pass's bit order).
        const u32 rbase = (u32)tsel << TB;
#pragma unroll
        for (int e = 0; e < EPT; e++)
            v[e] = __ldcs(stg + (rbase | (e << 9) | tid));
    }
    __syncthreads();
    if (pd.synth) {
        // amp(g) = (-i)^popc(g) * prod_q (bit_q ? sin(x_q/2) : cos(x_q/2))
        u32 gbase = 0;
#pragma unroll
        for (int i = 0; i < NFIX; i++)
            gbase |= ((u32)(tsel >> i) & 1u) << pd.fpos[i];
#pragma unroll
        for (int lb = 0; lb < 9; lb++)
            gbase |= ((u32)(tid >> lb) & 1u) << pd.fb[lb];
        const u32 f9 = 1u << pd.fb[9], f10 = 1u << pd.fb[10], f11 = 1u << pd.fb[11];
#pragma unroll
        for (int e = 0; e < EPT; e++) {
            u32 g = gbase | ((e & 1) ? f9 : 0u) | ((e & 2) ? f10 : 0u) | ((e & 4) ? f11 : 0u);
            float mag = 1.0f;
#pragma unroll
            for (int q = 0; q < NQ; q++)
                mag *= ((g >> q) & 1u) ? ss[q] : sc[q];
            int k = __popc(g) & 3;
            float re = (k == 0) ? mag : ((k == 2) ? -mag : 0.0f);
            float im = (k == 1) ? -mag : ((k == 3) ? mag : 0.0f);
            v[e] = pack2(re, im);
        }
    }

    const int nph = pd.nphases;
    for (int ph = 0; ph < nph; ph++) {
        if (ph > 0) {
#pragma unroll
            for (int e = 0; e < EPT; e++) {
                int j = jmap(ph, e, tid);
                v[e] = tile[SKEW(j)];
            }
        }
        const int lb0 = 9 - 3 * ph;
#pragma unroll
        for (int s = 0; s < 3; s++) {
            int lb = lb0 + s;
            if (pd.rotq[lb] >= 0) {
                u64 c00r = gmx[lb][0], c00i = gmx[lb][1], c01r = gmx[lb][2], c01i = gmx[lb][3];
                u64 c10r = gmx[lb][4], c10i = gmx[lb][5], c11r = gmx[lb][6], c11i = gmx[lb][7];
#pragma unroll
                for (int p = 0; p < 4; p++) {
                    int elo = ((p >> s) << (s + 1)) | (p & ((1 << s) - 1));
                    int ehi = elo | (1 << s);
                    u64 a = v[elo], bb = v[ehi];
                    u64 sa_ = swap64(a), sb_ = swap64(bb);
                    v[elo] = f2fma(c00r, a, f2fma(c00i, sa_, f2fma(c01r, bb, f2mul(c01i, sb_))));
                    v[ehi] = f2fma(c10r, a, f2fma(c10i, sa_, f2fma(c11r, bb, f2mul(c11i, sb_))));
                }
            }
        }
        if (ph > 0) __syncthreads();   // all tile reads done before overwrite
#pragma unroll
        for (int e = 0; e < EPT; e++) {
            int j = jmap(ph, e, tid);
            tile[SKEW(j)] = v[e];
        }
        __syncthreads();
    }

    // gather: f[j] = s[G(j)], G = composed CNOT chain (XOR-linear, local space)
    u32 srcbase = 0;
#pragma unroll
    for (int lb = 0; lb < 9; lb++)
        if ((tid >> lb) & 1) srcbase ^= pd.grow[lb];
    const u32 g9 = pd.grow[9], g10 = pd.grow[10], g11 = pd.grow[11];

    if (!pd.measure) {
        // write into NEXT pass's layout (coalesced by lane-qubit inheritance)
        u32 wbase = 0;
#pragma unroll
        for (int i = 0; i < NFIX; i++)
            wbase |= ((u32)(tsel >> i) & 1u) << pd.outfixpos[i];
#pragma unroll
        for (int lb = 0; lb < 9; lb++)
            wbase |= ((u32)(tid >> lb) & 1u) << pd.outpos[lb];
        const u32 w9 = 1u << pd.outpos[9], w10 = 1u << pd.outpos[10], w11 = 1u << pd.outpos[11];
#pragma unroll
        for (int e = 0; e < EPT; e++) {
            u32 src = srcbase ^ ((e & 1) ? g9 : 0u) ^ ((e & 2) ? g10 : 0u) ^ ((e & 4) ? g11 : 0u);
            u32 wa = wbase | ((e & 1) ? w9 : 0u) | ((e & 2) ? w10 : 0u) | ((e & 4) ? w11 : 0u);
            stg[wa] = tile[SKEW(src)];
        }
    } else {
        u32 gbase = 0;
#pragma unroll
        for (int i = 0; i < NFIX; i++)
            gbase |= ((u32)(tsel >> i) & 1u) << pd.fpos[i];
#pragma unroll
        for (int lb = 0; lb < 9; lb++)
            gbase |= ((u32)(tid >> lb) & 1u) << pd.fb[lb];
        float p8[EPT];
#pragma unroll
        for (int e = 0; e < EPT; e++) {
            u32 src = srcbase ^ ((e & 1) ? g9 : 0u) ^ ((e & 2) ? g10 : 0u) ^ ((e & 4) ? g11 : 0u);
            u64 val = tile[SKEW(src)];
            float2 c = *(float2*)&val;
            p8[e] = c.x * c.x + c.y * c.y;
        }
        float a0 = p8[0] + p8[1], a1 = p8[2] + p8[3], a2 = p8[4] + p8[5], a3 = p8[6] + p8[7];
        float b0 = a0 + a1, b1 = a2 + a3;
        float s_ = b0 + b1;
        float z0 = (p8[0] - p8[1]) + (p8[2] - p8[3]) + (p8[4] - p8[5]) + (p8[6] - p8[7]);
        float z1 = (a0 - a1) + (a2 - a3);
        float z2 = b0 - b1;
        float acc[NQ];
#pragma unroll
        for (int q = 0; q < NQ; q++) {
            float t = ((gbase >> q) & 1u) ? -s_ : s_;
            if (q == pd.fb[9])  t = z0;   // gbase bit is 0 there; z already signed
            if (q == pd.fb[10]) t = z1;
            if (q == pd.fb[11]) t = z2;
            acc[q] = t;
        }
#pragma unroll
        for (int q = 0; q < NQ; q++)
#pragma unroll
            for (int o = 16; o > 0; o >>= 1)
                acc[q] += __shfl_xor_sync(0xffffffffu, acc[q], o);
        if ((tid & 31) == 0) {
#pragma unroll
            for (int q = 0; q < NQ; q++)
                wred[tid >> 5][q] = acc[q];
        }
        __syncthreads();
        if (tid < NQ) {
            float sm = 0.0f;
#pragma unroll
            for (int wg = 0; wg < TPB / 32; wg++)
                sm += wred[wg][tid];
            g_part[((b << 4) | tsel) * NQ + tid] = sm;
        }
    }
}

__global__ void finalize_kernel(float* __restrict__ out)
{
    int i = blockIdx.x * blockDim.x + threadIdx.x;
    if (i < NB * NQ) {
        int b = i / NQ, q = i % NQ;
        float s = 0.0f;
#pragma unroll
        for (int t = 0; t < NT; t++)
            s += g_part[(b * NT + t) * NQ + q];
        out[i] = s;
    }
}

// ---------------------------------------------------------------------------
// Host scheduling: exact gate schedule proven in R4/R6 (pass A = Rot 0..11 +
// in-tile ring CNOTs; pass B = Rot 12..15 + deferred CNOTs; deferral commutes
// for all r<=6). New this round (isolated delta): the state between passes is
// stored bit-permuted so that the NEXT pass's free bits sit at address bits
// 0..11 -> every gmem read is purely linear; writes spread via outpos with
// lane-qubit inheritance for coalescing. Rot qubits are forced into the top
// local bits so pass B keeps nphases=2 under the R6 phase scheme.
// ---------------------------------------------------------------------------
static void compose_cnots(u32* grow, const u32* cm, const u32* tm, int ncn)
{
    for (int lb = 0; lb < TB; lb++) {
        u32 s = 1u << lb;
        for (int i = ncn - 1; i >= 0; i--)
            if (s & cm[i]) s ^= tm[i];
        grow[lb] = s;
    }
}

static void order_tile(const bool* inSet, const int* prevLanes,
                       const bool* prefSet, const bool* rotSet, int* fb)
{
    bool used[NQ] = {};
    int n = 0;
    if (prevLanes) {
        for (int i = 0; i < 5; i++) {
            int q = prevLanes[i];
            if (q >= 0 && inSet[q] && !used[q] && !rotSet[q]) { fb[n++] = q; used[q] = true; }
        }
    }
    while (n < 5) {
        int pick = -1;
        for (int tier = 0; tier < 4 && pick < 0; tier++)
            for (int q = 0; q < NQ && pick < 0; q++)
                if (inSet[q] && !used[q]) {
                    bool ok;
                    switch (tier) {
                        case 0: ok = prefSet && prefSet[q] && !rotSet[q]; break;
                        case 1: ok = !rotSet[q]; break;
                        case 2: ok = prefSet && prefSet[q]; break;
                        default: ok = true; break;
                    }
                    if (ok) pick = q;
                }
        fb[n++] = pick; used[pick] = true;
    }
    for (int q = 0; q < NQ; q++)            // middle: remaining non-rot
        if (inSet[q] && !used[q] && !rotSet[q]) { fb[n++] = q; used[q] = true; }
    for (int q = 0; q < NQ; q++)            // rot qubits last (high local bits)
        if (inSet[q] && !used[q]) { fb[n++] = q; used[q] = true; }
}

static void build_passes(PassDesc* pds)
{
    static bool tiles[NPASS][NQ], rots[NPASS][NQ];
    static int cms[NPASS][NQ], tms[NPASS][NQ], ncns[NPASS];
    static int fbs[NPASS][TB], fposs[NPASS][NFIX];

    for (int l = 0; l < NL; l++) {
        int r = (l % (NQ - 1)) + 1;
        bool inA[NQ];
        for (int q = 0; q < NQ; q++)
            inA[q] = (q <= 11 && (q + r) % NQ <= 11);

        int mA = 2 * l, mB = 2 * l + 1;
        for (int q = 0; q < NQ; q++) {
            tiles[mA][q] = (q < TB);
            rots[mA][q] = (q < TB);
        }
        ncns[mA] = 0;
        for (int q = 0; q < NQ; q++)
            if (inA[q]) { cms[mA][ncns[mA]] = q; tms[mA][ncns[mA]] = (q + r) % NQ; ncns[mA]++; }

        bool touched[NQ] = {};
        for (int q = TB; q < NQ; q++) touched[q] = true;
        for (int q = 0; q < NQ; q++)
            if (!inA[q]) { touched[q] = true; touched[(q + r) % NQ] = true; }
        int cnt = 0;
        for (int q = 0; q < NQ; q++) if (touched[q]) cnt++;
        for (int q = 0; q < NQ && cnt < TB; q++)
            if (!touched[q]) { touched[q] = true; cnt++; }
        for (int q = 0; q < NQ; q++) {
            tiles[mB][q] = touched[q];
            rots[mB][q] = (q >= TB);
        }
        ncns[mB] = 0;
        for (int q = 0; q < NQ; q++)
            if (!inA[q]) { cms[mB][ncns[mB]] = q; tms[mB][ncns[mB]] = (q + r) % NQ; ncns[mB]++; }
    }

    int prevLanes[5] = {-1, -1, -1, -1, -1};
    for (int m = 0; m < NPASS; m++) {
        bool pref[NQ]; bool hasPref = false;
        for (int q = 0; q < NQ; q++) pref[q] = false;
        if (m + 1 < NPASS) {
            for (int q = 0; q < NQ; q++) {
                bool p = tiles[m + 1][q];
                if (m + 2 < NPASS) p = p && tiles[m + 2][q];
                pref[q] = p;
            }
            hasPref = true;
        }
        order_tile(tiles[m], (m > 0) ? prevLanes : (const int*)0,
                   hasPref ? pref : (const bool*)0, rots[m], fbs[m]);
        for (int i = 0; i < 5; i++) prevLanes[i] = fbs[m][i];
        int xi = 0;
        for (int q = 0; q < NQ; q++)
            if (!tiles[m][q]) fposs[m][xi++] = q;
    }

    for (int m = 0; m < NPASS; m++) {
        PassDesc& pd = pds[m];
        memset(&pd, 0, sizeof(pd));
        pd.layer = m / 2;
        pd.synth = (m == 0);
        pd.measure = (m == NPASS - 1);
        pd.rev = (m & 1);
        int lq[NQ];
        for (int q = 0; q < NQ; q++) lq[q] = -1;
        for (int i = 0; i < TB; i++) { pd.fb[i] = fbs[m][i]; lq[fbs[m][i]] = i; }
        for (int i = 0; i < NFIX; i++) pd.fpos[i] = fposs[m][i];
        int minRot = TB;
        for (int i = 0; i < TB; i++) {
            pd.rotq[i] = rots[m][pd.fb[i]] ? pd.fb[i] : -1;
            if (pd.rotq[i] >= 0 && i < minRot) minRot = i;
        }
        pd.nphases = (TB - minRot + 2) / 3;   // A: 4, B: 2 (R6 phase scheme)
        u32 cm[NQ], tm[NQ];
        for (int i = 0; i < ncns[m]; i++) {
            cm[i] = 1u << lq[cms[m][i]];
            tm[i] = 1u << lq[tms[m][i]];
        }
        compose_cnots(pd.grow, cm, tm, ncns[m]);
        if (m + 1 < NPASS) {
            int pos[NQ];
            for (int i = 0; i < TB; i++)   pos[fbs[m + 1][i]] = i;
            for (int i = 0; i < NFIX; i++) pos[fposs[m + 1][i]] = TB + i;
            for (int i = 0; i < TB; i++)   pd.outpos[i] = pos[pd.fb[i]];
            for (int i = 0; i < NFIX; i++) pd.outfixpos[i] = pos[pd.fpos[i]];
        }
    }
}

extern "C" void kernel_launch(void* const* d_in, const int* in_sizes, int n_in,
                              void* d_out, int out_size)
{
    const float* x = (const float*)d_in[0];   // (512, 16)
    const float* w = (const float*)d_in[1];   // (6, 16, 3)
    float* out = (float*)d_out;               // (512, 16) float32

    PassDesc pds[NPASS];
    build_passes(pds);

    dim3 grid(NB * NT);
    for (int p = 0; p < NPASS; p++)
        pass_kernel<<<grid, TPB>>>(pds[p], x, w);

    finalize_kernel<<<(NB * NQ + 255) / 256, 256>>>(out);
}